// round 17
// baseline (speedup 1.0000x reference)
#include <cuda_runtime.h>
#include <cuda_bf16.h>
#include <cuda_fp8.h>
#include <cstdint>
#include <cstddef>

#define BATCH 512
#define NIN   2048
#define UNITS 4096
#define KTOT  6144
#define OFS   (BATCH*UNITS)

#define BM 128
#define BN 64
#define BK 128                 // fp8 K elements (=bytes) per stage
#define STAGES 4
#define NKS (KTOT/BK)          // 48
#define A_BYTES 16384u         // 128 m-rows x 128 B
#define STAGE_BYTES 24576u     // A 16K + B 8K
#define GEMM_SMEM (STAGES*STAGE_BYTES + 1024u)   // 99328 -> 2 CTAs/SM

#define SWZA(x) ((x) ^ (((x) >> 3) & 0x70u))     // 128-B pitch swizzle

#define WSCALE   64.0f
#define WSCALE_I 0.015625f     // 1/64

// prep block ranges (256-thread blocks)
#define NTRB ((KTOT/128)*(UNITS/64))   // 3072 : W transpose+fp8
#define NPKB ((BATCH*KTOT/8)/256)      // 1536 : A pack fp8, 8 elem/thread
#define NDGB (UNITS/256)               // 16   : diag

#define C_EL      (-70.6f)
#define C_THR     (-50.4f)
#define C_DTGLC   ((float)(30.0/281.0))
#define C_INVCAP  ((float)(1.0/281.0))
#define C_DTTAUW  ((float)(1.0/144.0))
#define C_DTATAUW ((float)(4.0/144.0))
#define C_BW      (0.0805f)
#define C_VRST    (-70.6f)
#define C_CLIP    (281.0f)

__device__ uint8_t g_A8[(size_t)BATCH * KTOT];          // [b][k] e4m3
__device__ uint8_t g_WT8[(size_t)UNITS * KTOT];         // [n][k] e4m3, x64
__device__ float g_diag[UNITS];

__device__ __forceinline__ uint32_t smem_u32(const void* p) {
    uint32_t a;
    asm("{ .reg .u64 t; cvta.to.shared.u64 t, %1; cvt.u32.u64 %0, t; }"
        : "=r"(a) : "l"(p));
    return a;
}
__device__ __forceinline__ void cp16(uint32_t saddr, const void* g) {
    asm volatile("cp.async.cg.shared.global [%0], [%1], 16;"
                 :: "r"(saddr), "l"(g));
}
__device__ __forceinline__ void ldmx4(uint32_t& r0, uint32_t& r1,
                                      uint32_t& r2, uint32_t& r3, uint32_t a) {
    asm volatile("ldmatrix.sync.aligned.m8n8.x4.shared.b16 {%0,%1,%2,%3}, [%4];"
                 : "=r"(r0), "=r"(r1), "=r"(r2), "=r"(r3) : "r"(a));
}
__device__ __forceinline__ void mma8(float& d0, float& d1, float& d2, float& d3,
                                     uint32_t a0, uint32_t a1, uint32_t a2, uint32_t a3,
                                     uint32_t b0, uint32_t b1) {
    asm volatile(
        "mma.sync.aligned.m16n8k32.row.col.f32.e4m3.e4m3.f32 "
        "{%0,%1,%2,%3}, {%4,%5,%6,%7}, {%8,%9}, {%0,%1,%2,%3};"
        : "+f"(d0), "+f"(d1), "+f"(d2), "+f"(d3)
        : "r"(a0), "r"(a1), "r"(a2), "r"(a3), "r"(b0), "r"(b1));
}
__device__ __forceinline__ uint32_t fp8b(float x) {
    return (uint32_t)__nv_cvt_float_to_fp8(x, __NV_SATFINITE, __NV_E4M3);
}

// ---------------- prep: W transpose->fp8(x64), A pack fp8, diag ----------
__global__ void __launch_bounds__(256)
prep_kernel(const float* __restrict__ inp, const float* __restrict__ z,
            const float* __restrict__ Win, const float* __restrict__ Wrec) {
    int blk = blockIdx.x;
    int tid = threadIdx.x;

    if (blk < NTRB) {
        // transpose 128k x 64n fp32 tile -> g_WT8[n][k] fp8 (x64)
        __shared__ uint32_t s[64][33];    // [n][k-word], pitch 33
        int k0 = (blk % (KTOT / 128)) * 128;
        int n0 = (blk / (KTOT / 128)) * 64;
        int R  = tid >> 4;                // 0..15
        int c4 = (tid & 15) * 4;          // n-local

        #pragma unroll
        for (int pp = 0; pp < 2; ++pp) {
            int kb = pp * 64 + R * 4;     // k-local base (4 rows)
            uint32_t q[4];
            #pragma unroll
            for (int i = 0; i < 4; ++i) {
                int k = k0 + kb + i;
                const float* src = (k < NIN)
                    ? (Win + (size_t)k * UNITS) : (Wrec + (size_t)(k - NIN) * UNITS);
                float4 f = *reinterpret_cast<const float4*>(src + n0 + c4);
                q[i] = fp8b(WSCALE * f.x) | (fp8b(WSCALE * f.y) << 8)
                     | (fp8b(WSCALE * f.z) << 16) | (fp8b(WSCALE * f.w) << 24);
            }
            // 4x4 byte transpose: out[j] = bytes j of q0..q3 (k ascending)
            uint32_t t0 = __byte_perm(q[0], q[1], 0x5140);
            uint32_t t1 = __byte_perm(q[0], q[1], 0x7362);
            uint32_t t2 = __byte_perm(q[2], q[3], 0x5140);
            uint32_t t3 = __byte_perm(q[2], q[3], 0x7362);
            int kw = pp * 16 + R;
            s[c4 + 0][kw] = __byte_perm(t0, t2, 0x5410);
            s[c4 + 1][kw] = __byte_perm(t0, t2, 0x7632);
            s[c4 + 2][kw] = __byte_perm(t1, t3, 0x5410);
            s[c4 + 3][kw] = __byte_perm(t1, t3, 0x7632);
        }
        __syncthreads();

        int kg = tid & 31, nl = tid >> 5;
        #pragma unroll
        for (int it = 0; it < 8; ++it) {
            int n = nl + it * 8;
            *reinterpret_cast<uint32_t*>(
                g_WT8 + (size_t)(n0 + n) * KTOT + k0 + kg * 4) = s[n][kg];
        }
    } else if (blk < NTRB + NPKB) {
        size_t e = ((size_t)(blk - NTRB) * 256 + tid) * 8;
        int b = (int)(e / KTOT);
        int k = (int)(e - (size_t)b * KTOT);
        const float* src = (k < NIN)
            ? (inp + (size_t)b * NIN + k)
            : (z + (size_t)b * UNITS + (k - NIN));
        float4 f0 = *reinterpret_cast<const float4*>(src);
        float4 f1 = *reinterpret_cast<const float4*>(src + 4);
        uint2 o;
        o.x = fp8b(f0.x) | (fp8b(f0.y) << 8) | (fp8b(f0.z) << 16) | (fp8b(f0.w) << 24);
        o.y = fp8b(f1.x) | (fp8b(f1.y) << 8) | (fp8b(f1.z) << 16) | (fp8b(f1.w) << 24);
        *reinterpret_cast<uint2*>(g_A8 + e) = o;
    } else {
        int n = (blk - NTRB - NPKB) * 256 + tid;
        __nv_fp8_e4m3 q;
        q.__x = (__nv_fp8_storage_t)fp8b(WSCALE * Wrec[(size_t)n * UNITS + n]);
        g_diag[n] = float(q) * WSCALE_I;
    }
}

// ---------------- stage loader (128 threads) ----------------
__device__ __forceinline__ void load_stage(uint32_t tiles, int tid,
                                           const uint8_t* Ag,
                                           const uint8_t* Bg,
                                           int ks, int s) {
    uint32_t abase = tiles + (uint32_t)s * STAGE_BYTES;
    uint32_t bbase = abase + A_BYTES;
    const uint8_t* ag = Ag + ks * BK;
    const uint8_t* bg = Bg + ks * BK;
    #pragma unroll
    for (int i = 0; i < 8; i++) {           // A: 128 m-rows x 8 chunks(16B)
        int id = tid + i * 128;
        int row = id >> 3, cg = id & 7;
        uint32_t off = SWZA((uint32_t)(row * 128 + cg * 16));
        cp16(abase + off, ag + (size_t)row * KTOT + cg * 16);
    }
    #pragma unroll
    for (int i = 0; i < 4; i++) {           // B: 64 n-rows x 8 chunks(16B)
        int id = tid + i * 128;
        int row = id >> 3, cg = id & 7;
        uint32_t off = SWZA((uint32_t)(row * 128 + cg * 16));
        cp16(bbase + off, bg + (size_t)row * KTOT + cg * 16);
    }
}

// ---------------- AdEx elementwise ----------------
__device__ __forceinline__ void adex_one(float it, float vo, float wo, float zo,
                                         int ro, float& nv, float& nz,
                                         float& nw, float& nr) {
    float ex = expf((vo - C_THR) * 0.5f);
    ex = fminf(ex, C_CLIP);
    float nv0 = vo - C_DTGLC * (vo - C_EL) + (2.0f * C_DTGLC) * ex
              + (it - wo) * C_INVCAP;
    nv = (zo > 0.5f) ? C_VRST : nv0;
    nw = wo - wo * C_DTTAUW + C_DTATAUW * (vo - C_EL) + C_BW * zo;
    bool sp = (nv > C_THR) && (ro <= 0);
    nz = sp ? 1.0f : 0.0f;
    int nri = ro - 1 + (sp ? 2 : 0);
    nri = nri < 0 ? 0 : (nri > 2 ? 2 : nri);
    nr = (float)nri;
}

// ---------------- FP8 GEMM: 4 warps, 128x64 CTA, 2 CTAs/SM ---------------
__global__ void __launch_bounds__(128, 2)
adex_gemm_kernel(const float* __restrict__ v_in, const int* __restrict__ r_in,
                 const float* __restrict__ w_in, const float* __restrict__ z_in,
                 float* __restrict__ out) {
    extern __shared__ char smem[];
    uint32_t tiles = (smem_u32(smem) + 1023u) & ~1023u;
    int tid = threadIdx.x;
    int wid = tid >> 5;
    int lane = tid & 31;

    int m0 = (blockIdx.x & 3) * BM;
    int n0 = (blockIdx.x >> 2) * BN;
    int wm = (wid & 1) * 64;     // 2 warps in M
    int wn = (wid >> 1) * 32;    // 2 warps in N

    const uint8_t* Ag = g_A8 + (size_t)m0 * KTOT;
    const uint8_t* Bg = g_WT8 + (size_t)n0 * KTOT;

    float acc[4][4][4];
    #pragma unroll
    for (int i = 0; i < 4; i++)
        #pragma unroll
        for (int j = 0; j < 4; j++)
            #pragma unroll
            for (int q = 0; q < 4; q++) acc[i][j][q] = 0.0f;

    #pragma unroll
    for (int s = 0; s < STAGES - 1; ++s) {
        load_stage(tiles, tid, Ag, Bg, s, s);
        asm volatile("cp.async.commit_group;");
    }

    int lrow = lane & 15;
    int lcg  = (lane >> 4) * 16;

    uint32_t aoff[4];
    #pragma unroll
    for (int mf = 0; mf < 4; ++mf)
        aoff[mf] = (uint32_t)((wm + mf * 16 + lrow) * 128 + lcg);
    uint32_t boff[2];
    #pragma unroll
    for (int p = 0; p < 2; ++p)
        boff[p] = (uint32_t)((wn + p * 16 + lrow) * 128 + lcg);

    for (int ks = 0; ks < NKS; ++ks) {
        int s = ks & (STAGES - 1);
        asm volatile("cp.async.wait_group %0;" :: "n"(2));
        __syncthreads();

        int kn = ks + STAGES - 1;
        if (kn < NKS) load_stage(tiles, tid, Ag, Bg, kn, kn & (STAGES - 1));
        asm volatile("cp.async.commit_group;");

        uint32_t abase = tiles + (uint32_t)s * STAGE_BYTES;
        uint32_t bbase = abase + A_BYTES;

        uint32_t af[2][4][4], bfr[2][4][2];

        // preload fragments for kk=0 (k32 per step)
        #pragma unroll
        for (int mf = 0; mf < 4; ++mf)
            ldmx4(af[0][mf][0], af[0][mf][1], af[0][mf][2], af[0][mf][3],
                  abase + SWZA(aoff[mf]));
        #pragma unroll
        for (int p = 0; p < 2; ++p) {
            uint32_t r0, r1, r2, r3;
            ldmx4(r0, r1, r2, r3, bbase + SWZA(boff[p]));
            bfr[0][p * 2 + 0][0] = r0; bfr[0][p * 2 + 0][1] = r2;
            bfr[0][p * 2 + 1][0] = r1; bfr[0][p * 2 + 1][1] = r3;
        }

        #pragma unroll
        for (int kk = 0; kk < BK / 32; ++kk) {   // 4 k-steps of k32
            int cur = kk & 1, nxt = cur ^ 1;
            bool pre = (kk < BK / 32 - 1);
            uint32_t kb = (uint32_t)((kk + 1) * 32);   // +32 bytes = k32

            #define MMA_AT(MF,NF) \
                mma8(acc[MF][NF][0], acc[MF][NF][1], \
                     acc[MF][NF][2], acc[MF][NF][3], \
                     af[cur][MF][0], af[cur][MF][1], \
                     af[cur][MF][2], af[cur][MF][3], \
                     bfr[cur][NF][0], bfr[cur][NF][1])

            MMA_AT(0, 0); MMA_AT(0, 1);
            if (pre) ldmx4(af[nxt][0][0], af[nxt][0][1], af[nxt][0][2],
                           af[nxt][0][3], abase + SWZA(aoff[0] + kb));
            MMA_AT(0, 2); MMA_AT(0, 3);
            if (pre) ldmx4(af[nxt][1][0], af[nxt][1][1], af[nxt][1][2],
                           af[nxt][1][3], abase + SWZA(aoff[1] + kb));
            MMA_AT(1, 0); MMA_AT(1, 1);
            if (pre) ldmx4(af[nxt][2][0], af[nxt][2][1], af[nxt][2][2],
                           af[nxt][2][3], abase + SWZA(aoff[2] + kb));
            MMA_AT(1, 2); MMA_AT(1, 3);
            if (pre) ldmx4(af[nxt][3][0], af[nxt][3][1], af[nxt][3][2],
                           af[nxt][3][3], abase + SWZA(aoff[3] + kb));
            MMA_AT(2, 0); MMA_AT(2, 1);
            if (pre) {
                uint32_t r0, r1, r2, r3;
                ldmx4(r0, r1, r2, r3, bbase + SWZA(boff[0] + kb));
                bfr[nxt][0][0] = r0; bfr[nxt][0][1] = r2;
                bfr[nxt][1][0] = r1; bfr[nxt][1][1] = r3;
            }
            MMA_AT(2, 2); MMA_AT(2, 3);
            if (pre) {
                uint32_t r0, r1, r2, r3;
                ldmx4(r0, r1, r2, r3, bbase + SWZA(boff[1] + kb));
                bfr[nxt][2][0] = r0; bfr[nxt][2][1] = r2;
                bfr[nxt][3][0] = r1; bfr[nxt][3][1] = r3;
            }
            MMA_AT(3, 0); MMA_AT(3, 1); MMA_AT(3, 2); MMA_AT(3, 3);
            #undef MMA_AT
        }
    }

    // ------------- epilogue (acc holds 64*i_t) -------------
    int gid = lane >> 2;
    int qn  = (lane & 3) * 2;

    #pragma unroll
    for (int mf = 0; mf < 4; ++mf) {
        #pragma unroll
        for (int g = 0; g < 2; ++g) {
            int b = m0 + wm + mf * 16 + g * 8 + gid;
            size_t rowbase = (size_t)b * UNITS + n0 + wn;
            #pragma unroll
            for (int nf = 0; nf < 4; ++nf) {
                size_t ofs = rowbase + nf * 8 + qn;
                int ncol = n0 + wn + nf * 8 + qn;
                float2 vv = *reinterpret_cast<const float2*>(v_in + ofs);
                float2 ww = *reinterpret_cast<const float2*>(w_in + ofs);
                float2 zz = *reinterpret_cast<const float2*>(z_in + ofs);
                int2   rr = *reinterpret_cast<const int2*>(r_in + ofs);
                float2 dg = *reinterpret_cast<const float2*>(g_diag + ncol);
                float i0 = acc[mf][nf][g * 2 + 0] * WSCALE_I - zz.x * dg.x;
                float i1 = acc[mf][nf][g * 2 + 1] * WSCALE_I - zz.y * dg.y;
                float2 ov, oz, ow, orr;
                adex_one(i0, vv.x, ww.x, zz.x, rr.x, ov.x, oz.x, ow.x, orr.x);
                adex_one(i1, vv.y, ww.y, zz.y, rr.y, ov.y, oz.y, ow.y, orr.y);
                *reinterpret_cast<float2*>(out + 0 * (size_t)OFS + ofs) = ov;
                *reinterpret_cast<float2*>(out + 1 * (size_t)OFS + ofs) = oz;
                *reinterpret_cast<float2*>(out + 2 * (size_t)OFS + ofs) = ow;
                *reinterpret_cast<float2*>(out + 3 * (size_t)OFS + ofs) = orr;
            }
        }
    }
}

// ---------------- launch ----------------
extern "C" void kernel_launch(void* const* d_in, const int* in_sizes, int n_in,
                              void* d_out, int out_size) {
    const float* inputs = (const float*)d_in[0];
    const float* v      = (const float*)d_in[1];
    const int*   r      = (const int*)d_in[2];
    const float* w      = (const float*)d_in[3];
    const float* z      = (const float*)d_in[4];
    const float* Win    = (const float*)d_in[5];
    const float* Wrec   = (const float*)d_in[6];
    float* out = (float*)d_out;
    (void)in_sizes; (void)n_in; (void)out_size;

    cudaFuncSetAttribute(adex_gemm_kernel,
                         cudaFuncAttributeMaxDynamicSharedMemorySize, GEMM_SMEM);

    prep_kernel<<<NTRB + NPKB + NDGB, 256>>>(inputs, z, Win, Wrec);
    adex_gemm_kernel<<<256, 128, GEMM_SMEM>>>(v, r, w, z, out);
}